// round 1
// baseline (speedup 1.0000x reference)
#include <cuda_runtime.h>
#include <math.h>

// Problem constants
#define BATCH 4
#define NCLS 3
#define HH 96
#define WW 96
#define NPIX (HH * WW)           // 9216
#define NLISTS 16                // (batch 4) x (class 2) x (type: pred/label 2)
#define NCOMBO 16                // (batch 4) x (class 2) x (dir: fwd/rev 2)
#define NBINS 18051              // max d^2 = 2*95*95 = 18050

// Scratch (device globals; no runtime allocation)
__device__ unsigned short g_lists[NLISTS][NPIX];  // packed coords (row<<8)|col
__device__ int g_cnt[NLISTS];
__device__ int g_maxd2[NCOMBO];
__device__ int g_hist[NCOMBO][NBINS];

// list index: ((i*2 + (cls-1))*2 + type), type 0=pred mask, 1=label mask
__device__ __forceinline__ int list_idx(int i, int jj, int t) {
    return ((i * 2 + jj) * 2) + t;
}

// ---------------------------------------------------------------------------
// Kernel 0: zero scratch
// ---------------------------------------------------------------------------
__global__ void zero_kernel() {
    int idx = blockIdx.x * blockDim.x + threadIdx.x;
    int total = NCOMBO * NBINS;
    int stride = gridDim.x * blockDim.x;
    int* h = &g_hist[0][0];
    for (int k = idx; k < total; k += stride) h[k] = 0;
    if (idx < NLISTS) g_cnt[idx] = 0;
    if (idx < NCOMBO) g_maxd2[idx] = 0;
}

// ---------------------------------------------------------------------------
// Kernel 1: argmax over classes + compact coordinate lists for both masks
// ---------------------------------------------------------------------------
__global__ void build_kernel(const float* __restrict__ preds,
                             const int* __restrict__ labels) {
    int idx = blockIdx.x * blockDim.x + threadIdx.x;
    if (idx >= BATCH * NPIX) return;
    int i = idx / NPIX;
    int p = idx - i * NPIX;

    const float* base = preds + (size_t)i * NCLS * NPIX + p;
    float v0 = base[0];
    float v1 = base[NPIX];
    float v2 = base[2 * NPIX];
    // argmax with first-max tie-break (softmax is monotone -> argmax of logits)
    int pc = 0; float bv = v0;
    if (v1 > bv) { bv = v1; pc = 1; }
    if (v2 > bv) { bv = v2; pc = 2; }

    unsigned short packed = (unsigned short)(((p / WW) << 8) | (p % WW));

    if (pc >= 1) {
        int li = list_idx(i, pc - 1, 0);
        int pos = atomicAdd(&g_cnt[li], 1);
        g_lists[li][pos] = packed;
    }
    int lb = labels[i * NPIX + p];
    if (lb >= 1) {
        int li = list_idx(i, lb - 1, 1);
        int pos = atomicAdd(&g_cnt[li], 1);
        g_lists[li][pos] = packed;
    }
}

// ---------------------------------------------------------------------------
// Kernel 2: brute-force nearest-neighbor min-d^2 per source pixel -> histogram
// combo c: i = c>>2, jj = (c>>1)&1 (class j = jj+1), dir = c&1
// dir 0 (fwd): source = pred mask, target = label mask
// dir 1 (rev): source = label mask, target = pred mask
// ---------------------------------------------------------------------------
__global__ void dist_kernel() {
    int c = blockIdx.x;
    int i = c >> 2;
    int jj = (c >> 1) & 1;
    int dir = c & 1;
    int sLi = list_idx(i, jj, dir == 0 ? 0 : 1);
    int tLi = list_idx(i, jj, dir == 0 ? 1 : 0);
    int sCnt = g_cnt[sLi];
    int tCnt = g_cnt[tLi];

    int s = blockIdx.y * blockDim.x + threadIdx.x;
    if ((int)(blockIdx.y * blockDim.x) >= sCnt) return;  // whole block idle

    __shared__ unsigned short tile[NPIX];  // full target list (<= 18 KB)
    for (int k = threadIdx.x; k < tCnt; k += blockDim.x)
        tile[k] = g_lists[tLi][k];
    __syncthreads();

    if (s >= sCnt) return;

    unsigned short pk = g_lists[sLi][s];
    int srow = pk >> 8;
    int scol = pk & 255;

    int best = 0x7fffffff;
    int k = 0;
    // chunked loop with early exit (exact hit: pred==label pixel is common)
    for (; k + 16 <= tCnt; k += 16) {
        if (best == 0) break;
        #pragma unroll
        for (int u = 0; u < 16; u++) {
            int q = tile[k + u];
            int dx = srow - (q >> 8);
            int dy = scol - (q & 255);
            int d2 = dx * dx + dy * dy;
            best = min(best, d2);
        }
    }
    if (best != 0) {
        for (; k < tCnt; k++) {
            int q = tile[k];
            int dx = srow - (q >> 8);
            int dy = scol - (q & 255);
            int d2 = dx * dx + dy * dy;
            best = min(best, d2);
        }
    }

    atomicAdd(&g_hist[c][best], 1);
    atomicMax(&g_maxd2[c], best);
}

// ---------------------------------------------------------------------------
// Kernel 3: per-combo stats from histograms, then accumulate + finalize
// one warp per combo; thread 0 assembles the 3x(3x5) output
// ---------------------------------------------------------------------------
__global__ void final_kernel(float* __restrict__ out) {
    __shared__ float s_mx[NCOMBO], s_mean[NCOMBO], s_p[NCOMBO];

    int w = threadIdx.x >> 5;
    int lane = threadIdx.x & 31;

    if (w < NCOMBO) {
        int c = w;
        int md2 = g_maxd2[c];
        int n = 0;
        float sum = 0.f;
        for (int b = lane; b <= md2; b += 32) {
            int h = g_hist[c][b];
            n += h;
            sum += (float)h * sqrtf((float)b);
        }
        for (int off = 16; off; off >>= 1) {
            n += __shfl_down_sync(0xffffffffu, n, off);
            sum += __shfl_down_sync(0xffffffffu, sum, off);
        }
        if (lane == 0) {
            float mx = 0.f, mean = 0.f, pcl = 0.f;
            if (n > 0) {
                mx = sqrtf((float)md2);
                mean = sum / (float)n;
                float pos = (95.0f / 100.0f) * (float)(n - 1);
                int lo = (int)floorf(pos);
                int hi = (int)ceilf(pos);
                float frac = pos - (float)lo;
                int cum = 0;
                float vlo = 0.f, vhi = 0.f;
                bool gotlo = false;
                for (int b = 0; b <= md2; b++) {
                    cum += g_hist[c][b];
                    if (!gotlo && cum > lo) { vlo = sqrtf((float)b); gotlo = true; }
                    if (cum > hi) { vhi = sqrtf((float)b); break; }
                }
                pcl = vlo * (1.0f - frac) + vhi * frac;
            }
            s_mx[c] = mx;
            s_mean[c] = mean;
            s_p[c] = pcl;
        }
    }
    __syncthreads();

    if (threadIdx.x == 0) {
        float M[3][5] = {{0}}, F[3][5] = {{0}}, R[3][5] = {{0}};
        for (int i = 0; i < BATCH; i++) {
            for (int jj = 0; jj < 2; jj++) {
                int j = jj + 1;
                int cf = (i << 2) | (jj << 1);   // fwd combo
                int cr = cf | 1;                 // rev combo
                float fmx = s_mx[cf],   rmx = s_mx[cr];
                float fme = s_mean[cf], rme = s_mean[cr];
                float fp  = s_p[cf],    rp  = s_p[cr];
                F[0][j] += fmx; R[0][j] += rmx; M[0][j] += fmaxf(fmx, rmx);
                F[1][j] += fme; R[1][j] += rme; M[1][j] += fmaxf(fme, rme);
                // faithful to source bug: FHD gets both directions' percentiles,
                // RHD percentile row stays zero
                F[2][j] += fp + rp;
                M[2][j] += fmaxf(fp, rp);
            }
        }
        float* mats[3] = {&M[0][0], &F[0][0], &R[0][0]};
        for (int t = 0; t < 3; t++) {
            float* X = mats[t];
            for (int r = 0; r < 3; r++) {
                for (int c2 = 0; c2 < 3; c2++) X[r * 5 + c2] *= 0.25f;  // / batch(4)
                X[r * 5 + 3] = (X[r * 5 + 0] + X[r * 5 + 1] + X[r * 5 + 2]) / 3.0f;
                X[r * 5 + 4] = (X[r * 5 + 1] + X[r * 5 + 2]) * 0.5f;
            }
            for (int k = 0; k < 15; k++) out[t * 15 + k] = X[k];
        }
    }
}

// ---------------------------------------------------------------------------
extern "C" void kernel_launch(void* const* d_in, const int* in_sizes, int n_in,
                              void* d_out, int out_size) {
    const float* preds = (const float*)d_in[0];
    const int* labels = (const int*)d_in[1];
    float* out = (float*)d_out;

    zero_kernel<<<256, 256>>>();
    build_kernel<<<(BATCH * NPIX + 255) / 256, 256>>>(preds, labels);
    dist_kernel<<<dim3(NCOMBO, (NPIX + 255) / 256), 256>>>();
    final_kernel<<<1, 512>>>(out);
}

// round 2
// speedup vs baseline: 3.4586x; 3.4586x over previous
#include <cuda_runtime.h>
#include <math.h>

#define BATCH 4
#define NCLS 3
#define HH 96
#define WW 96
#define NPIX (HH * WW)           // 9216
#define NCOMBO 16                // batch(4) x class(2) x dir(2)
#define NBINS 18051              // max d^2 = 95^2 + 95^2
#define THREADS 256

// per-combo stats: {max, mean, percentile}
__device__ float g_stats[NCOMBO][3];

// Dynamic smem layout:
//   int    hist[NBINS]   72204 B
//   ushort g[NPIX]       18432 B   (1-D column squared distances, 65535 = empty col sentinel)
//   uchar  pcls[NPIX]     9216 B   (argmax class map)
//   uchar  lab[NPIX]      9216 B   (label class map)
#define SMEM_BYTES (NBINS * 4 + NPIX * 2 + NPIX + NPIX)

// ---------------------------------------------------------------------------
// One block per combo c: i = c>>2, class j = ((c>>1)&1)+1, dir = c&1
// dir 0 (fwd): source = pred mask, target = label mask
// dir 1 (rev): source = label mask, target = pred mask
// ---------------------------------------------------------------------------
__global__ __launch_bounds__(THREADS, 1)
void combo_kernel(const float* __restrict__ preds,
                  const int* __restrict__ labels) {
    extern __shared__ char smem[];
    int* hist = (int*)smem;
    unsigned short* g = (unsigned short*)(hist + NBINS);
    unsigned char* pcls = (unsigned char*)(g + NPIX);
    unsigned char* lab = pcls + NPIX;

    __shared__ int s_maxd2;
    __shared__ int s_n[THREADS];
    __shared__ float s_sum[THREADS];

    const int c = blockIdx.x;
    const int i = c >> 2;
    const int j = ((c >> 1) & 1) + 1;
    const int dir = c & 1;
    const int tid = threadIdx.x;

    if (tid == 0) s_maxd2 = 0;

    // zero histogram
    for (int k = tid; k < NBINS; k += THREADS) hist[k] = 0;

    // build class maps (argmax of logits == argmax of softmax)
    const float* base = preds + (size_t)i * NCLS * NPIX;
    const int* lbase = labels + i * NPIX;
    for (int p = tid; p < NPIX; p += THREADS) {
        float v0 = base[p];
        float v1 = base[p + NPIX];
        float v2 = base[p + 2 * NPIX];
        int pc = 0; float bv = v0;
        if (v1 > bv) { bv = v1; pc = 1; }
        if (v2 > bv) { bv = v2; pc = 2; }
        pcls[p] = (unsigned char)pc;
        lab[p] = (unsigned char)lbase[p];
    }
    __syncthreads();

    const unsigned char* smap = (dir == 0) ? pcls : lab;   // source mask map
    const unsigned char* tmap = (dir == 0) ? lab : pcls;   // target mask map

    // pass 1: per-column 1-D squared distance to nearest target row (two sweeps)
    if (tid < WW) {
        const int col = tid;
        int last = -1000;
        #pragma unroll 4
        for (int r = 0; r < HH; r++) {
            if (tmap[r * WW + col] == j) last = r;
            int d = r - last;
            g[r * WW + col] = (unsigned short)min(65535, d * d);
        }
        last = 1000;
        #pragma unroll 4
        for (int r = HH - 1; r >= 0; r--) {
            if (tmap[r * WW + col] == j) last = r;
            int d = last - r;
            int v = min(65535, d * d);
            if (v < (int)g[r * WW + col]) g[r * WW + col] = (unsigned short)v;
        }
    }
    __syncthreads();

    // pass 2: per source pixel, min over columns with outward pruning
    for (int p = tid; p < NPIX; p += THREADS) {
        if (smap[p] != j) continue;
        int r = p / WW;
        int cc = p - r * WW;
        const unsigned short* grow = g + r * WW;
        int best = grow[cc];
        for (int dc = 1; dc < WW; dc++) {
            int d2 = dc * dc;
            if (d2 >= best) break;
            int cl = cc - dc, cr = cc + dc;
            if (cl >= 0) { int v = d2 + (int)grow[cl]; if (v < best) best = v; }
            if (cr < WW) { int v = d2 + (int)grow[cr]; if (v < best) best = v; }
        }
        if (best >= NBINS) best = NBINS - 1;  // safety (unreachable for nonempty mask)
        atomicAdd(&hist[best], 1);
        atomicMax(&s_maxd2, best);
    }
    __syncthreads();

    // stats: deterministic tree reduction of n and sum(sqrt(d2))
    const int maxd2 = s_maxd2;
    int n_loc = 0;
    float sum_loc = 0.f;
    for (int b = tid; b <= maxd2; b += THREADS) {
        int h = hist[b];
        n_loc += h;
        sum_loc += (float)h * sqrtf((float)b);
    }
    s_n[tid] = n_loc;
    s_sum[tid] = sum_loc;
    __syncthreads();
    for (int off = THREADS / 2; off > 0; off >>= 1) {
        if (tid < off) {
            s_n[tid] += s_n[tid + off];
            s_sum[tid] += s_sum[tid + off];
        }
        __syncthreads();
    }

    if (tid == 0) {
        int n = s_n[0];
        float mx = 0.f, mean = 0.f, pcl = 0.f;
        if (n > 0) {
            mx = sqrtf((float)maxd2);
            mean = s_sum[0] / (float)n;
            float pos = 0.95f * (float)(n - 1);
            int lo = (int)floorf(pos);
            int hi = (int)ceilf(pos);
            float frac = pos - (float)lo;
            int cum = 0;
            float vlo = 0.f, vhi = 0.f;
            bool gotlo = false;
            for (int b = 0; b <= maxd2; b++) {
                cum += hist[b];
                if (!gotlo && cum > lo) { vlo = sqrtf((float)b); gotlo = true; }
                if (cum > hi) { vhi = sqrtf((float)b); break; }
            }
            pcl = vlo * (1.0f - frac) + vhi * frac;
        }
        g_stats[c][0] = mx;
        g_stats[c][1] = mean;
        g_stats[c][2] = pcl;
    }
}

// ---------------------------------------------------------------------------
// Finalize: combine 16 combo stats into MHD/FHD/RHD (3 x 3 x 5 floats)
// ---------------------------------------------------------------------------
__global__ void final_kernel(float* __restrict__ out) {
    if (threadIdx.x != 0) return;
    float M[3][5] = {{0}}, F[3][5] = {{0}}, R[3][5] = {{0}};
    for (int i = 0; i < BATCH; i++) {
        for (int jj = 0; jj < 2; jj++) {
            int j = jj + 1;
            int cf = (i << 2) | (jj << 1);   // fwd
            int cr = cf | 1;                 // rev
            float fmx = g_stats[cf][0], rmx = g_stats[cr][0];
            float fme = g_stats[cf][1], rme = g_stats[cr][1];
            float fp  = g_stats[cf][2], rp  = g_stats[cr][2];
            F[0][j] += fmx; R[0][j] += rmx; M[0][j] += fmaxf(fmx, rmx);
            F[1][j] += fme; R[1][j] += rme; M[1][j] += fmaxf(fme, rme);
            // faithful to source bug: FHD gets both directions' percentiles,
            // RHD percentile row stays zero
            F[2][j] += fp + rp;
            M[2][j] += fmaxf(fp, rp);
        }
    }
    float* mats[3] = {&M[0][0], &F[0][0], &R[0][0]};
    for (int t = 0; t < 3; t++) {
        float* X = mats[t];
        for (int r = 0; r < 3; r++) {
            for (int c2 = 0; c2 < 3; c2++) X[r * 5 + c2] *= 0.25f;  // / batch
            X[r * 5 + 3] = (X[r * 5 + 0] + X[r * 5 + 1] + X[r * 5 + 2]) / 3.0f;
            X[r * 5 + 4] = (X[r * 5 + 1] + X[r * 5 + 2]) * 0.5f;
        }
        for (int k = 0; k < 15; k++) out[t * 15 + k] = X[k];
    }
}

// ---------------------------------------------------------------------------
extern "C" void kernel_launch(void* const* d_in, const int* in_sizes, int n_in,
                              void* d_out, int out_size) {
    const float* preds = (const float*)d_in[0];
    const int* labels = (const int*)d_in[1];
    float* out = (float*)d_out;

    cudaFuncSetAttribute(combo_kernel,
                         cudaFuncAttributeMaxDynamicSharedMemorySize, SMEM_BYTES);

    combo_kernel<<<NCOMBO, THREADS, SMEM_BYTES>>>(preds, labels);
    final_kernel<<<1, 32>>>(out);
}

// round 3
// speedup vs baseline: 3.4805x; 1.0063x over previous
#include <cuda_runtime.h>
#include <math.h>

#define BATCH 4
#define NCLS 3
#define HH 96
#define WW 96
#define NPIX (HH * WW)           // 9216
#define NCOMBO 16                // batch(4) x class(2) x dir(2)
#define HCAP 2048                // in-smem histogram bins (d^2 < 2048); rest -> overflow list
#define THREADS 256

// cross-block state
__device__ float g_stats[NCOMBO][3];      // {max, mean, percentile}
__device__ int g_done = 0;                // last-block-done counter (reset each run)
__device__ int g_ovf_cnt[NCOMBO];         // overflow counts (reset by owning block)
__device__ unsigned short g_ovf[NCOMBO][NPIX];  // overflow d^2 values (expected unused)

// Dynamic smem layout:
//   int    hist[HCAP]    8192 B
//   ushort gF[NPIX]     18432 B   (forward 1-D column sq-dist, then merged EDT)
//   ushort gB[NPIX]     18432 B   (backward 1-D column sq-dist)
//   uchar  pcls[NPIX]    9216 B
//   uchar  lab[NPIX]     9216 B
#define SMEM_BYTES (HCAP * 4 + NPIX * 2 + NPIX * 2 + NPIX + NPIX)

// ---------------------------------------------------------------------------
// One block per combo c: i = c>>2, class j = ((c>>1)&1)+1, dir = c&1
// dir 0 (fwd): source = pred mask, target = label mask; dir 1: swapped.
// Last finishing block assembles the 3x(3x5) output.
// ---------------------------------------------------------------------------
__global__ __launch_bounds__(THREADS, 1)
void hausdorff_kernel(const float* __restrict__ preds,
                      const int* __restrict__ labels,
                      float* __restrict__ out) {
    extern __shared__ char smem[];
    int* hist = (int*)smem;
    unsigned short* gF = (unsigned short*)(hist + HCAP);
    unsigned short* gB = gF + NPIX;
    unsigned char* pcls = (unsigned char*)(gB + NPIX);
    unsigned char* lab = pcls + NPIX;

    __shared__ int s_maxd2;
    __shared__ int s_n[THREADS];
    __shared__ float s_sum[THREADS];
    __shared__ int s_last;

    const int c = blockIdx.x;
    const int i = c >> 2;
    const int j = ((c >> 1) & 1) + 1;
    const int dir = c & 1;
    const int tid = threadIdx.x;
    const int lane = tid & 31;

    if (tid == 0) { s_maxd2 = 0; g_ovf_cnt[c] = 0; }

    // zero histogram (8 iters of STS)
    for (int k = tid; k < HCAP; k += THREADS) hist[k] = 0;

    // build class maps, vectorized (argmax of logits == argmax of softmax)
    {
        const float* base = preds + (size_t)i * NCLS * NPIX;
        const float4* b0 = (const float4*)base;
        const float4* b1 = (const float4*)(base + NPIX);
        const float4* b2 = (const float4*)(base + 2 * NPIX);
        const int4* l4 = (const int4*)(labels + i * NPIX);
        for (int q = tid; q < NPIX / 4; q += THREADS) {
            float4 a = __ldg(&b0[q]);
            float4 b = __ldg(&b1[q]);
            float4 d = __ldg(&b2[q]);
            int4 L = __ldg(&l4[q]);
            uchar4 pc, lb;
            {
                int k0 = 0; float bv = a.x;
                if (b.x > bv) { bv = b.x; k0 = 1; }
                if (d.x > bv) k0 = 2;
                pc.x = (unsigned char)k0;
            }
            {
                int k0 = 0; float bv = a.y;
                if (b.y > bv) { bv = b.y; k0 = 1; }
                if (d.y > bv) k0 = 2;
                pc.y = (unsigned char)k0;
            }
            {
                int k0 = 0; float bv = a.z;
                if (b.z > bv) { bv = b.z; k0 = 1; }
                if (d.z > bv) k0 = 2;
                pc.z = (unsigned char)k0;
            }
            {
                int k0 = 0; float bv = a.w;
                if (b.w > bv) { bv = b.w; k0 = 1; }
                if (d.w > bv) k0 = 2;
                pc.w = (unsigned char)k0;
            }
            lb.x = (unsigned char)L.x; lb.y = (unsigned char)L.y;
            lb.z = (unsigned char)L.z; lb.w = (unsigned char)L.w;
            *(uchar4*)&pcls[q * 4] = pc;
            *(uchar4*)&lab[q * 4] = lb;
        }
    }
    __syncthreads();

    const unsigned char* smap = (dir == 0) ? pcls : lab;   // source mask map
    const unsigned char* tmap = (dir == 0) ? lab : pcls;   // target mask map

    // pass 1: per-column 1-D sq-dist, forward (threads 0..95) and backward
    // (threads 96..191) concurrently into separate arrays
    if (tid < WW) {
        const int col = tid;
        int last = -1000;
        #pragma unroll 4
        for (int r = 0; r < HH; r++) {
            if (tmap[r * WW + col] == j) last = r;
            int d = min(r - last, 255);
            gF[r * WW + col] = (unsigned short)(d * d);
        }
    } else if (tid < 2 * WW) {
        const int col = tid - WW;
        int last = 1000;
        #pragma unroll 4
        for (int r = HH - 1; r >= 0; r--) {
            if (tmap[r * WW + col] == j) last = r;
            int d = min(last - r, 255);
            gB[r * WW + col] = (unsigned short)(d * d);
        }
    }
    __syncthreads();

    // merge: gF = min(gF, gB), SIMD halfword (18 iters)
    {
        unsigned int* pf = (unsigned int*)gF;
        const unsigned int* pb = (const unsigned int*)gB;
        for (int q = tid; q < NPIX / 2; q += THREADS)
            pf[q] = __vminu2(pf[q], pb[q]);
    }
    __syncthreads();

    // pass 2: per source pixel, min over columns with outward pruning.
    // NPIX/THREADS = 36 full iterations -> warp-uniform loop, ballot legal.
    for (int p = tid; p < NPIX; p += THREADS) {
        bool valid = (smap[p] == j);
        int best = 0x7fffffff;
        if (valid) {
            int r = p / WW;
            int cc = p - r * WW;
            const unsigned short* grow = gF + r * WW;
            best = grow[cc];
            for (int dc = 1; dc < WW; dc++) {
                int d2 = dc * dc;
                if (d2 >= best) break;
                int cl = cc - dc, cr = cc + dc;
                if (cl >= 0) { int v = d2 + (int)grow[cl]; if (v < best) best = v; }
                if (cr < WW) { int v = d2 + (int)grow[cr]; if (v < best) best = v; }
            }
        }
        // warp-aggregate the dominant d^2 == 0 bin
        unsigned zmask = __ballot_sync(0xffffffffu, valid && best == 0);
        if (lane == 0 && zmask) atomicAdd(&hist[0], __popc(zmask));
        if (valid && best > 0) {
            if (best < HCAP) {
                atomicAdd(&hist[best], 1);
                atomicMax(&s_maxd2, best);
            } else {
                int pos = atomicAdd(&g_ovf_cnt[c], 1);
                g_ovf[c][pos] = (unsigned short)min(best, 65535);
            }
        }
    }
    __syncthreads();

    // stats: deterministic tree reduction of n and sum(sqrt(d2)) over hist
    const int maxd2 = s_maxd2;
    int n_loc = 0;
    float sum_loc = 0.f;
    for (int b = tid; b <= maxd2; b += THREADS) {
        int h = hist[b];
        n_loc += h;
        sum_loc += (float)h * sqrtf((float)b);
    }
    s_n[tid] = n_loc;
    s_sum[tid] = sum_loc;
    __syncthreads();
    for (int off = THREADS / 2; off > 0; off >>= 1) {
        if (tid < off) {
            s_n[tid] += s_n[tid + off];
            s_sum[tid] += s_sum[tid + off];
        }
        __syncthreads();
    }

    if (tid == 0) {
        int n_hist = s_n[0];
        float sum = s_sum[0];
        int m = g_ovf_cnt[c];          // overflow entries (expected 0)
        if (m > 0) {                    // exact slow path, correctness only
            // serial selection sort ascending
            for (int a = 0; a < m - 1; a++) {
                int mi = a;
                for (int b = a + 1; b < m; b++)
                    if (g_ovf[c][b] < g_ovf[c][mi]) mi = b;
                unsigned short t = g_ovf[c][a];
                g_ovf[c][a] = g_ovf[c][mi];
                g_ovf[c][mi] = t;
            }
            for (int a = 0; a < m; a++) sum += sqrtf((float)g_ovf[c][a]);
        }
        int n = n_hist + m;
        float mx = 0.f, mean = 0.f, pcl = 0.f;
        if (n > 0) {
            int truemax = (m > 0) ? (int)g_ovf[c][m - 1] : maxd2;
            mx = sqrtf((float)truemax);
            mean = sum / (float)n;
            float pos = 0.95f * (float)(n - 1);
            int lo = (int)floorf(pos);
            int hi = (int)ceilf(pos);
            float frac = pos - (float)lo;
            float vlo = 0.f, vhi = 0.f;
            {
                int cum = 0;
                bool gotlo = false, gothi = false;
                for (int b = 0; b <= maxd2; b++) {
                    cum += hist[b];
                    if (!gotlo && cum > lo) { vlo = sqrtf((float)b); gotlo = true; }
                    if (cum > hi) { vhi = sqrtf((float)b); gothi = true; break; }
                }
                if (!gotlo) vlo = sqrtf((float)g_ovf[c][lo - n_hist]);
                if (!gothi) vhi = sqrtf((float)g_ovf[c][hi - n_hist]);
            }
            pcl = vlo * (1.0f - frac) + vhi * frac;
        }
        g_stats[c][0] = mx;
        g_stats[c][1] = mean;
        g_stats[c][2] = pcl;
        __threadfence();
        int t = atomicAdd(&g_done, 1);
        s_last = (t == NCOMBO - 1) ? 1 : 0;
    }
    __syncthreads();

    // last block assembles the output
    if (s_last && tid == 0) {
        __threadfence();
        g_done = 0;  // reset for next graph replay
        float M[3][5] = {{0}}, F[3][5] = {{0}}, R[3][5] = {{0}};
        for (int bi = 0; bi < BATCH; bi++) {
            for (int jj = 0; jj < 2; jj++) {
                int jc = jj + 1;
                int cf = (bi << 2) | (jj << 1);
                int cr = cf | 1;
                float fmx = g_stats[cf][0], rmx = g_stats[cr][0];
                float fme = g_stats[cf][1], rme = g_stats[cr][1];
                float fp  = g_stats[cf][2], rp  = g_stats[cr][2];
                F[0][jc] += fmx; R[0][jc] += rmx; M[0][jc] += fmaxf(fmx, rmx);
                F[1][jc] += fme; R[1][jc] += rme; M[1][jc] += fmaxf(fme, rme);
                // faithful to source bug: FHD gets both directions' percentiles,
                // RHD percentile row stays zero
                F[2][jc] += fp + rp;
                M[2][jc] += fmaxf(fp, rp);
            }
        }
        float* mats[3] = {&M[0][0], &F[0][0], &R[0][0]};
        for (int t2 = 0; t2 < 3; t2++) {
            float* X = mats[t2];
            for (int r = 0; r < 3; r++) {
                for (int c2 = 0; c2 < 3; c2++) X[r * 5 + c2] *= 0.25f;  // / batch
                X[r * 5 + 3] = (X[r * 5 + 0] + X[r * 5 + 1] + X[r * 5 + 2]) / 3.0f;
                X[r * 5 + 4] = (X[r * 5 + 1] + X[r * 5 + 2]) * 0.5f;
            }
            for (int k = 0; k < 15; k++) out[t2 * 15 + k] = X[k];
        }
    }
}

// ---------------------------------------------------------------------------
extern "C" void kernel_launch(void* const* d_in, const int* in_sizes, int n_in,
                              void* d_out, int out_size) {
    const float* preds = (const float*)d_in[0];
    const int* labels = (const int*)d_in[1];
    float* out = (float*)d_out;

    cudaFuncSetAttribute(hausdorff_kernel,
                         cudaFuncAttributeMaxDynamicSharedMemorySize, SMEM_BYTES);

    hausdorff_kernel<<<NCOMBO, THREADS, SMEM_BYTES>>>(preds, labels, out);
}